// round 13
// baseline (speedup 1.0000x reference)
#include <cuda_runtime.h>
#include <cuda_bf16.h>

// diag-embed: out[i, j, k] = (j == k) ? x[i, j] : 0
// x: [8192, 176] fp32, out: [8192, 176, 176] fp32 (~1.015 GB of stores).
//
// FINAL champion (R4, re-validated R10/R12). Runs at the measured ~6.4 TB/s
// pure-write HBM ceiling of this GB300; kernel time equals the theoretical
// 1.015 GB transfer time. Load-bearing properties (each falsification-tested
// across 12 rounds):
//   - 1184 blocks x 256 threads = 8 blocks/SM, 2048 thr/SM (~97% occ),
//     fine-grained whole-grid interleaved store stream
//     (beat slabs R7, warp-tiles R8, 4x512 repack R12-neutral)
//   - branchless diagonal insertion: unconditional L2-hot LDG + 4 selects
//     (beat divergent branch R1-R3)
//   - 32-bit magic div/mod (64-bit cost shown in R1; cheaper variants R6/R8
//     gained nothing - issue never binding)
//   - __stcs STG.128, lane-consecutive (beat STG.256 R11, stwt R9,
//     per-lane stride-2 R5, two-pass fill+scatter R8)
//   - unroll 8 for independent stores in flight

#define D_MODEL 176u
#define CPR 44u            // float4 chunks per output row
#define BLOCKS 1184u       // 148 SMs * 8 blocks -> perfectly balanced
#define THREADS 256u

__global__ __launch_bounds__(THREADS) void diag_embed_kernel(
        const float* __restrict__ x,
        float4* __restrict__ out,
        unsigned n4) {
    const unsigned stride = BLOCKS * THREADS;
    unsigned g = blockIdx.x * THREADS + threadIdx.x;

    #pragma unroll 8
    for (; g < n4; g += stride) {
        unsigned rowg = g / CPR;                 // 32-bit magic div
        unsigned q    = g - rowg * CPR;          // chunk within row
        unsigned row  = rowg % D_MODEL;          // diag position in row

        // Unconditional: warp's chunks span <=2 rows -> 1-2 L2-hot sectors.
        float xv = __ldg(x + rowg);

        unsigned c0 = q * 4u;                    // column of v.x
        float4 v;
        v.x = (c0        == row) ? xv : 0.f;
        v.y = (c0 + 1u   == row) ? xv : 0.f;
        v.z = (c0 + 2u   == row) ? xv : 0.f;
        v.w = (c0 + 3u   == row) ? xv : 0.f;

        __stcs(out + g, v);                      // streaming store
    }
}

extern "C" void kernel_launch(void* const* d_in, const int* in_sizes, int n_in,
                              void* d_out, int out_size) {
    const float* x = (const float*)d_in[0];
    float4* out = (float4*)d_out;

    unsigned n4 = (unsigned)(out_size / 4);      // 63,438,848 float4 chunks

    diag_embed_kernel<<<BLOCKS, THREADS>>>(x, out, n4);
}

// round 14
// speedup vs baseline: 1.0016x; 1.0016x over previous
#include <cuda_runtime.h>
#include <cuda_bf16.h>

// diag-embed: out[i, j, k] = (j == k) ? x[i, j] : 0
// x: [8192, 176] fp32, out: [8192, 176, 176] fp32 (~1.015 GB of stores).
//
// FINAL champion (R4; re-validated R10/R12/R13, profile bit-stable).
// 1.015 GB / 158.4 us kernel = 6.41 TB/s sustained — the measured pure-write
// HBM ceiling of this GB300. Load-bearing properties, each tested by
// falsification across 13 rounds:
//   - 1184 blocks x 256 threads = 8 blocks/SM, 2048 thr/SM (~99% occ),
//     fine-grained whole-grid interleaved store stream
//     (beat slabs R7, warp-tiles R8; packing-invariant R12)
//   - branchless diagonal insertion: unconditional L2-hot LDG + 4 selects
//     (beat divergent branch R1-R3; LDG already 1 instr/warp, 1-2 sectors)
//   - 32-bit magic div/mod (indexing never binding: R6, R8, R11)
//   - __stcs STG.128 lane-consecutive (beat STG.256 R11 - wider stores
//     REDUCED DRAM%; cs==wt R9; fused beats fill+scatter by 70us R8)
//   - unroll 8 for independent stores in flight

#define D_MODEL 176u
#define CPR 44u            // float4 chunks per output row
#define BLOCKS 1184u       // 148 SMs * 8 blocks -> perfectly balanced
#define THREADS 256u

__global__ __launch_bounds__(THREADS) void diag_embed_kernel(
        const float* __restrict__ x,
        float4* __restrict__ out,
        unsigned n4) {
    const unsigned stride = BLOCKS * THREADS;
    unsigned g = blockIdx.x * THREADS + threadIdx.x;

    #pragma unroll 8
    for (; g < n4; g += stride) {
        unsigned rowg = g / CPR;                 // 32-bit magic div
        unsigned q    = g - rowg * CPR;          // chunk within row
        unsigned row  = rowg % D_MODEL;          // diag position in row

        // Unconditional: warp's chunks span <=2 rows -> 1-2 L2-hot sectors.
        float xv = __ldg(x + rowg);

        unsigned c0 = q * 4u;                    // column of v.x
        float4 v;
        v.x = (c0        == row) ? xv : 0.f;
        v.y = (c0 + 1u   == row) ? xv : 0.f;
        v.z = (c0 + 2u   == row) ? xv : 0.f;
        v.w = (c0 + 3u   == row) ? xv : 0.f;

        __stcs(out + g, v);                      // streaming store
    }
}

extern "C" void kernel_launch(void* const* d_in, const int* in_sizes, int n_in,
                              void* d_out, int out_size) {
    const float* x = (const float*)d_in[0];
    float4* out = (float4*)d_out;

    unsigned n4 = (unsigned)(out_size / 4);      // 63,438,848 float4 chunks

    diag_embed_kernel<<<BLOCKS, THREADS>>>(x, out, n4);
}

// round 15
// speedup vs baseline: 1.0034x; 1.0018x over previous
#include <cuda_runtime.h>
#include <cuda_bf16.h>

// diag-embed: out[i, j, k] = (j == k) ? x[i, j] : 0
// x: [8192, 176] fp32, out: [8192, 176, 176] fp32 (~1.015 GB of stores).
//
// R15: champion body (R4, 4x re-validated at ~158us kernel / 6.4 TB/s) with
// the last unisolated micro-knob: unroll 8 -> 16. 16 independent STG.128s
// per warp per back-edge (deeper store MLP, half the branch frequency).
// Regs ~22->~30, still <=32 so 2048 thr/SM occupancy is preserved.
// All proven load-bearing properties frozen:
//   - 1184 x 256 (8 blocks/SM), fine-grained whole-grid interleave
//   - branchless diagonal insertion (unconditional L2-hot LDG + 4 selects)
//   - 32-bit magic div/mod
//   - __stcs STG.128 lane-consecutive

#define D_MODEL 176u
#define CPR 44u            // float4 chunks per output row
#define BLOCKS 1184u       // 148 SMs * 8 blocks -> perfectly balanced
#define THREADS 256u

__global__ __launch_bounds__(THREADS) void diag_embed_kernel(
        const float* __restrict__ x,
        float4* __restrict__ out,
        unsigned n4) {
    const unsigned stride = BLOCKS * THREADS;
    unsigned g = blockIdx.x * THREADS + threadIdx.x;

    #pragma unroll 16
    for (; g < n4; g += stride) {
        unsigned rowg = g / CPR;                 // 32-bit magic div
        unsigned q    = g - rowg * CPR;          // chunk within row
        unsigned row  = rowg % D_MODEL;          // diag position in row

        // Unconditional: warp's chunks span <=2 rows -> 1-2 L2-hot sectors.
        float xv = __ldg(x + rowg);

        unsigned c0 = q * 4u;                    // column of v.x
        float4 v;
        v.x = (c0        == row) ? xv : 0.f;
        v.y = (c0 + 1u   == row) ? xv : 0.f;
        v.z = (c0 + 2u   == row) ? xv : 0.f;
        v.w = (c0 + 3u   == row) ? xv : 0.f;

        __stcs(out + g, v);                      // streaming store
    }
}

extern "C" void kernel_launch(void* const* d_in, const int* in_sizes, int n_in,
                              void* d_out, int out_size) {
    const float* x = (const float*)d_in[0];
    float4* out = (float4*)d_out;

    unsigned n4 = (unsigned)(out_size / 4);      // 63,438,848 float4 chunks

    diag_embed_kernel<<<BLOCKS, THREADS>>>(x, out, n4);
}